// round 1
// baseline (speedup 1.0000x reference)
#include <cuda_runtime.h>
#include <math.h>

#define N_NODES 11201
#define E_PER_R 100000
#define N_REL   5
#define NNZ     (N_REL * E_PER_R)
#define NSEG    (N_REL * N_NODES)
#define D       512
#define KBIG    (N_REL * D)   // 2560
#define BATCH   32
#define FRAME   1200
#define OUTW    1712

// ---------------- scratch (device globals; no allocation) ----------------
__device__ float g_x[N_NODES * D];
__device__ float g_h[N_NODES * D];
__device__ float g_emb[N_NODES * D];
__device__ float g_y[(size_t)N_NODES * KBIG];

__device__ int   g_counts[NSEG];
__device__ int   g_rowptr[NSEG + 1];
__device__ int   g_cursor[NSEG];
__device__ int   g_ccol[NNZ];
__device__ float g_cval[NNZ];

__device__ float g_c1[BATCH * 2048];
__device__ float g_c2[BATCH * D];
__device__ float g_c3[BATCH * D];
__device__ float g_q[BATCH * D];

__device__ __forceinline__ float* bufptr(int s) {
    switch (s) {
        case 1: return g_c1;
        case 2: return g_c2;
        case 3: return g_c3;
        case 4: return g_q;
        case 5: return g_emb;
    }
    return nullptr;
}

// ---------------- init ----------------
__global__ void zero_k(float* out) {
    int i = blockIdx.x * 256 + threadIdx.x;           // grid covers 65536
    if (i < NSEG) g_counts[i] = 0;
    if (i < BATCH * 2048) g_c1[i] = 0.f;
    if (i < BATCH * D) { g_c2[i] = 0.f; g_c3[i] = 0.f; g_q[i] = 0.f; }
    if (i < BATCH * OUTW) out[i] = 0.f;
}

__global__ void build_x_k(const float* __restrict__ frame_emb,
                          const float* __restrict__ role_emb,
                          const int* __restrict__ fe_ids) {
    int row = blockIdx.x;
    int t = threadIdx.x; // 128
    const float4* src;
    if (row < FRAME) src = (const float4*)(frame_emb + (size_t)row * D);
    else             src = (const float4*)(role_emb + (size_t)fe_ids[row - FRAME] * D);
    ((float4*)(g_x + (size_t)row * D))[t] = src[t];
}

// ---------------- CSR build ----------------
__global__ void count_k(const int* __restrict__ rows) {
    int e = blockIdx.x * 256 + threadIdx.x;
    if (e < NNZ) {
        int r = e / E_PER_R;
        atomicAdd(&g_counts[r * N_NODES + rows[e]], 1);
    }
}

__global__ void scan_k() {
    __shared__ int s[1024];
    const int CH = 55; // 1024*55 >= 56005
    int t = threadIdx.x;
    int base = t * CH;
    int sum = 0;
#pragma unroll 4
    for (int i = 0; i < CH; ++i) {
        int idx = base + i;
        if (idx < NSEG) sum += g_counts[idx];
    }
    s[t] = sum;
    __syncthreads();
    for (int off = 1; off < 1024; off <<= 1) {
        int v = (t >= off) ? s[t - off] : 0;
        __syncthreads();
        s[t] += v;
        __syncthreads();
    }
    int run = s[t] - sum; // exclusive prefix of this thread's chunk
    for (int i = 0; i < CH; ++i) {
        int idx = base + i;
        if (idx < NSEG) {
            g_rowptr[idx] = run;
            g_cursor[idx] = run;
            run += g_counts[idx];
        }
    }
    if (t == 1023) g_rowptr[NSEG] = s[1023];
}

__global__ void scatter_k(const int* __restrict__ rows,
                          const int* __restrict__ cols,
                          const float* __restrict__ vals) {
    int e = blockIdx.x * 256 + threadIdx.x;
    if (e < NNZ) {
        int r = e / E_PER_R;
        int seg = r * N_NODES + rows[e];
        int pos = atomicAdd(&g_cursor[seg], 1);
        g_ccol[pos] = cols[e];
        g_cval[pos] = vals[e];
    }
}

// ---------------- SpMM: y[row, r*512+d] = sum_e val * x[col][d] ----------------
__global__ void __launch_bounds__(128) spmm_k(int insel) {
    const float4* __restrict__ x4 = (const float4*)(insel ? g_h : g_x);
    int seg = blockIdx.x;
    int r = seg / N_NODES;
    int row = seg - r * N_NODES;
    int s = g_rowptr[seg];
    int e = g_rowptr[seg + 1];
    int t = threadIdx.x;

    float4 acc0 = make_float4(0.f, 0.f, 0.f, 0.f);
    float4 acc1 = make_float4(0.f, 0.f, 0.f, 0.f);

    int i = s;
    for (; i + 1 < e; i += 2) {
        int c0 = __ldg(&g_ccol[i]);
        int c1 = __ldg(&g_ccol[i + 1]);
        float v0 = __ldg(&g_cval[i]);
        float v1 = __ldg(&g_cval[i + 1]);
        float4 t0 = x4[(size_t)c0 * 128 + t];
        float4 t1 = x4[(size_t)c1 * 128 + t];
        acc0.x += v0 * t0.x; acc0.y += v0 * t0.y; acc0.z += v0 * t0.z; acc0.w += v0 * t0.w;
        acc1.x += v1 * t1.x; acc1.y += v1 * t1.y; acc1.z += v1 * t1.z; acc1.w += v1 * t1.w;
    }
    if (i < e) {
        int c0 = __ldg(&g_ccol[i]);
        float v0 = __ldg(&g_cval[i]);
        float4 t0 = x4[(size_t)c0 * 128 + t];
        acc0.x += v0 * t0.x; acc0.y += v0 * t0.y; acc0.z += v0 * t0.z; acc0.w += v0 * t0.w;
    }
    acc0.x += acc1.x; acc0.y += acc1.y; acc0.z += acc1.z; acc0.w += acc1.w;
    ((float4*)g_y)[(size_t)row * (KBIG / 4) + r * (D / 4) + t] = acc0;
}

// ---------------- big GEMM: C = tanh(g_y[M,2560] @ W[2560,512]) ----------------
#define BM 128
#define BN 64
#define BKK 32
__global__ void __launch_bounds__(256) gemm_tanh_k(const float* __restrict__ W, int outsel) {
    __shared__ float As[BKK][BM + 4]; // [32][132], store A transposed
    __shared__ float Bs[BKK][BN];

    const float* __restrict__ A = g_y;
    float* __restrict__ C = outsel ? g_emb : g_h;

    int tid = threadIdx.x;
    int m0 = blockIdx.x * BM;
    int n0 = blockIdx.y * BN;
    int tx = tid & 15;       // 0..15 (n)
    int ty = tid >> 4;       // 0..15 (m)

    int a_row = tid >> 3;          // 0..31
    int a_col = (tid & 7) * 4;     // k within tile
    int b_row = tid >> 4;          // 0..15
    int b_col = (tid & 15) * 4;

    float acc[8][4];
#pragma unroll
    for (int i = 0; i < 8; ++i)
#pragma unroll
        for (int j = 0; j < 4; ++j) acc[i][j] = 0.f;

    for (int k0 = 0; k0 < KBIG; k0 += BKK) {
#pragma unroll
        for (int g = 0; g < 4; ++g) {
            int m = m0 + a_row + g * 32;
            float4 v = make_float4(0.f, 0.f, 0.f, 0.f);
            if (m < N_NODES) v = *(const float4*)(A + (size_t)m * KBIG + k0 + a_col);
            As[a_col + 0][a_row + g * 32] = v.x;
            As[a_col + 1][a_row + g * 32] = v.y;
            As[a_col + 2][a_row + g * 32] = v.z;
            As[a_col + 3][a_row + g * 32] = v.w;
        }
#pragma unroll
        for (int g = 0; g < 2; ++g) {
            int kk = b_row + g * 16;
            *(float4*)&Bs[kk][b_col] = *(const float4*)(W + (size_t)(k0 + kk) * D + n0 + b_col);
        }
        __syncthreads();
#pragma unroll
        for (int kk = 0; kk < BKK; ++kk) {
            float4 a0 = *(const float4*)&As[kk][ty * 8];
            float4 a1 = *(const float4*)&As[kk][ty * 8 + 4];
            float4 b  = *(const float4*)&Bs[kk][tx * 4];
            float am[8] = {a0.x, a0.y, a0.z, a0.w, a1.x, a1.y, a1.z, a1.w};
            float bn[4] = {b.x, b.y, b.z, b.w};
#pragma unroll
            for (int i = 0; i < 8; ++i)
#pragma unroll
                for (int j = 0; j < 4; ++j) acc[i][j] += am[i] * bn[j];
        }
        __syncthreads();
    }
#pragma unroll
    for (int i = 0; i < 8; ++i) {
        int m = m0 + ty * 8 + i;
        if (m < N_NODES) {
#pragma unroll
            for (int j = 0; j < 4; ++j)
                C[(size_t)m * D + n0 + tx * 4 + j] = tanhf(acc[i][j]);
        }
    }
}

// ---------------- small GEMM (M=32), split-K with atomic accumulate ----------------
// C[32,N](+=) A[32,K] @ W[K,N]  (BT=false)   or   A[32,K] @ Wb[N,K]^T (BT=true)
template <bool BT>
__global__ void __launch_bounds__(256) sgemm_k(int asel, const float* Ain,
                                               int wsel, const float* Win,
                                               int csel, float* Cin,
                                               int K, int N, int ldc) {
    __shared__ float sA[32 * 33];
    __shared__ float sW[64 * 33]; // also holds [32][65] layout (2080 <= 2112)

    const float* __restrict__ A = (asel < 0) ? Ain : bufptr(asel);
    const float* __restrict__ W = (wsel < 0) ? Win : bufptr(wsel);
    float* __restrict__ C = (csel < 0) ? Cin : bufptr(csel);

    int tid = threadIdx.x;
    int tx = tid & 31;   // j
    int ty = tid >> 5;   // 0..7 (b group)
    int j0 = blockIdx.x * 64;
    int k0 = blockIdx.y * 256;

    float acc[4][2];
#pragma unroll
    for (int i = 0; i < 4; ++i) { acc[i][0] = 0.f; acc[i][1] = 0.f; }

    for (int kc = 0; kc < 256; kc += 32) {
        int kb = k0 + kc;
        for (int i = tid; i < 32 * 32; i += 256) {
            int kk = i & 31, bb = i >> 5;
            sA[kk * 33 + bb] = A[(size_t)bb * K + kb + kk];
        }
        if (!BT) {
            for (int i = tid; i < 64 * 32; i += 256) {
                int jl = i & 63, kk = i >> 6;
                int j = j0 + jl;
                sW[kk * 65 + jl] = (j < N) ? W[(size_t)(kb + kk) * N + j] : 0.f;
            }
        } else {
            for (int i = tid; i < 64 * 32; i += 256) {
                int kk = i & 31, jl = i >> 5;
                int j = j0 + jl;
                sW[jl * 33 + kk] = (j < N) ? W[(size_t)j * K + kb + kk] : 0.f;
            }
        }
        __syncthreads();
#pragma unroll 8
        for (int kk = 0; kk < 32; ++kk) {
            float w0 = BT ? sW[tx * 33 + kk] : sW[kk * 65 + tx];
            float w1 = BT ? sW[(tx + 32) * 33 + kk] : sW[kk * 65 + tx + 32];
#pragma unroll
            for (int i = 0; i < 4; ++i) {
                float a = sA[kk * 33 + ty + 8 * i];
                acc[i][0] += a * w0;
                acc[i][1] += a * w1;
            }
        }
        __syncthreads();
    }
#pragma unroll
    for (int i = 0; i < 4; ++i) {
        int b = ty + 8 * i;
        int j = j0 + tx;
        if (j < N) atomicAdd(&C[(size_t)b * ldc + j], acc[i][0]);
        j = j0 + tx + 32;
        if (j < N) atomicAdd(&C[(size_t)b * ldc + j], acc[i][1]);
    }
}

__global__ void bias_act_k(int csel, const float* __restrict__ bias, int N, int act) {
    int idx = blockIdx.x * 256 + threadIdx.x;
    if (idx >= BATCH * N) return;
    float* C = bufptr(csel);
    int j = idx % N;
    float v = C[idx] + bias[j];
    if (act == 1) v = fmaxf(v, 0.f);
    else if (act == 2) v = tanhf(v);
    C[idx] = v;
}

__global__ void fgather_k(const int* __restrict__ gold, const int* __restrict__ flist,
                          float* __restrict__ out) {
    int b = blockIdx.x;
    int t = threadIdx.x; // 128
    int label = flist[b * 16 + gold[b]];
    ((float4*)(out + (size_t)b * OUTW + FRAME))[t] =
        ((const float4*)(g_emb + (size_t)label * D))[t];
}

// ---------------- launcher ----------------
extern "C" void kernel_launch(void* const* d_in, const int* in_sizes, int n_in,
                              void* d_out, int out_size) {
    const float* target_span = (const float*)d_in[0];
    const float* frame_emb   = (const float*)d_in[1];
    const float* role_emb    = (const float*)d_in[2];
    const float* rel_W0      = (const float*)d_in[3];
    const float* rel_W1      = (const float*)d_in[4];
    const float* span_W1     = (const float*)d_in[5];
    const float* span_b1     = (const float*)d_in[6];
    const float* span_W2     = (const float*)d_in[7];
    const float* span_b2     = (const float*)d_in[8];
    const float* fp_W1       = (const float*)d_in[9];
    const float* fp_b1       = (const float*)d_in[10];
    const float* fp_W2       = (const float*)d_in[11];
    const float* fp_b2       = (const float*)d_in[12];
    const float* adj_vals    = (const float*)d_in[13];
    const int*   fe_ids      = (const int*)d_in[14];
    const int*   adj_rows    = (const int*)d_in[15];
    const int*   adj_cols    = (const int*)d_in[16];
    const int*   gold        = (const int*)d_in[17];
    const int*   flist       = (const int*)d_in[18];
    float* out = (float*)d_out;

    zero_k<<<256, 256>>>(out);
    build_x_k<<<N_NODES, 128>>>(frame_emb, role_emb, fe_ids);

    // CSR (shared by both layers)
    count_k<<<(NNZ + 255) / 256, 256>>>(adj_rows);
    scan_k<<<1, 1024>>>();
    scatter_k<<<(NNZ + 255) / 256, 256>>>(adj_rows, adj_cols, adj_vals);

    // Layer 1: y = A x ; h = tanh(y @ W0_flat)
    spmm_k<<<NSEG, 128>>>(0);
    gemm_tanh_k<<<dim3((N_NODES + BM - 1) / BM, D / BN), 256>>>(rel_W0, 0);
    // Layer 2
    spmm_k<<<NSEG, 128>>>(1);
    gemm_tanh_k<<<dim3((N_NODES + BM - 1) / BM, D / BN), 256>>>(rel_W1, 1);

    // target_node = relu(ts @ W1 + b1) @ W2 + b2
    sgemm_k<false><<<dim3(2048 / 64, 2048 / 256), 256>>>(-1, target_span, -1, span_W1, 1, nullptr, 2048, 2048, 2048);
    bias_act_k<<<(BATCH * 2048 + 255) / 256, 256>>>(1, span_b1, 2048, 1);
    sgemm_k<false><<<dim3(D / 64, 2048 / 256), 256>>>(1, nullptr, -1, span_W2, 2, nullptr, 2048, D, D);
    bias_act_k<<<(BATCH * D + 255) / 256, 256>>>(2, span_b2, D, 0);
    // Q = tanh(relu(tn @ fpW1 + b) @ fpW2 + b)
    sgemm_k<false><<<dim3(D / 64, D / 256), 256>>>(2, nullptr, -1, fp_W1, 3, nullptr, D, D, D);
    bias_act_k<<<(BATCH * D + 255) / 256, 256>>>(3, fp_b1, D, 1);
    sgemm_k<false><<<dim3(D / 64, D / 256), 256>>>(3, nullptr, -1, fp_W2, 4, nullptr, D, D, D);
    bias_act_k<<<(BATCH * D + 255) / 256, 256>>>(4, fp_b2, D, 2);

    // pred[b, n<1200] = Q[b,:] . emb[n,:]   (B^T small gemm, accumulate into out)
    sgemm_k<true><<<dim3((FRAME + 63) / 64, D / 256), 256>>>(4, nullptr, 5, nullptr, -1, out, D, FRAME, OUTW);
    // frame_node gather into out[:, 1200:1712]
    fgather_k<<<BATCH, 128>>>(gold, flist, out);
}

// round 3
// speedup vs baseline: 2.2401x; 2.2401x over previous
#include <cuda_runtime.h>
#include <cstdint>
#include <math.h>

#define N_NODES 11201
#define E_PER_R 100000
#define N_REL   5
#define NNZ     (N_REL * E_PER_R)
#define NSEG    (N_REL * N_NODES)
#define D       512
#define KBIG    (N_REL * D)   // 2560
#define BATCH   32
#define FRAME   1200
#define OUTW    1712
#define SCAN_NB 219           // ceil(56005/256)
#define NCHUNK  80            // KBIG/32

// ---------------- scratch (device globals; no allocation) ----------------
__device__ float g_x[N_NODES * D];
__device__ float g_h[N_NODES * D];
__device__ float g_emb[N_NODES * D];
__device__ float g_y[(size_t)N_NODES * KBIG];
__device__ float g_wt0[(size_t)D * KBIG];   // W0^T, [512][2560], tf32-rounded
__device__ float g_wt1[(size_t)D * KBIG];

__device__ int   g_counts[NSEG];
__device__ int   g_rowptr[NSEG + 1];
__device__ int   g_cursor[NSEG];
__device__ int   g_bsum[256];
__device__ int   g_ccol[NNZ];
__device__ float g_cval[NNZ];

__device__ float g_c1[BATCH * 2048];
__device__ float g_c2[BATCH * D];
__device__ float g_c3[BATCH * D];
__device__ float g_q[BATCH * D];

__device__ __forceinline__ float* bufptr(int s) {
    switch (s) {
        case 1: return g_c1;
        case 2: return g_c2;
        case 3: return g_c3;
        case 4: return g_q;
        case 5: return g_emb;
    }
    return nullptr;
}

__device__ __forceinline__ uint32_t smem_u32(const void* p) {
    uint32_t a;
    asm("{ .reg .u64 t; cvta.to.shared.u64 t, %1; cvt.u32.u64 %0, t; }" : "=r"(a) : "l"(p));
    return a;
}
__device__ __forceinline__ float tf32r(float x) {
    float y;
    asm("cvt.rna.tf32.f32 %0, %1;" : "=f"(y) : "f"(x));
    return y;
}

// ---------------- init ----------------
__global__ void zero_k(float* out) {
    int i = blockIdx.x * 256 + threadIdx.x;           // grid covers 65536
    if (i < NSEG) g_counts[i] = 0;
    if (i < BATCH * 2048) g_c1[i] = 0.f;
    if (i < BATCH * D) { g_c2[i] = 0.f; g_c3[i] = 0.f; g_q[i] = 0.f; }
    if (i < BATCH * OUTW) out[i] = 0.f;
}

__global__ void build_x_k(const float* __restrict__ frame_emb,
                          const float* __restrict__ role_emb,
                          const int* __restrict__ fe_ids) {
    int row = blockIdx.x;
    int t = threadIdx.x; // 128
    const float4* src;
    if (row < FRAME) src = (const float4*)(frame_emb + (size_t)row * D);
    else             src = (const float4*)(role_emb + (size_t)fe_ids[row - FRAME] * D);
    ((float4*)(g_x + (size_t)row * D))[t] = src[t];
}

// W[2560][512] -> WT[512][2560], tf32-rounded
__global__ void wtrans_k(const float* __restrict__ W, float* __restrict__ WT) {
    __shared__ float t[32][33];
    int k0 = blockIdx.x * 32, n0 = blockIdx.y * 32;
    int tx = threadIdx.x, ty = threadIdx.y; // 32 x 8
#pragma unroll
    for (int i = ty; i < 32; i += 8)
        t[i][tx] = W[(size_t)(k0 + i) * D + n0 + tx];
    __syncthreads();
#pragma unroll
    for (int i = ty; i < 32; i += 8)
        WT[(size_t)(n0 + i) * KBIG + k0 + tx] = tf32r(t[tx][i]);
}

// ---------------- CSR build ----------------
__global__ void count_k(const int* __restrict__ rows) {
    int e = blockIdx.x * 256 + threadIdx.x;
    if (e < NNZ) {
        int r = e / E_PER_R;
        atomicAdd(&g_counts[r * N_NODES + rows[e]], 1);
    }
}

__global__ void scan1_k() {
    __shared__ int s[256];
    int i = blockIdx.x * 256 + threadIdx.x;
    int v = (i < NSEG) ? g_counts[i] : 0;
    s[threadIdx.x] = v;
    __syncthreads();
#pragma unroll
    for (int off = 1; off < 256; off <<= 1) {
        int a = (threadIdx.x >= off) ? s[threadIdx.x - off] : 0;
        __syncthreads();
        s[threadIdx.x] += a;
        __syncthreads();
    }
    if (i < NSEG) g_rowptr[i] = s[threadIdx.x] - v;  // exclusive within block
    if (threadIdx.x == 255) g_bsum[blockIdx.x] = s[255];
}

__global__ void scan2_k() {
    __shared__ int s[256];
    int v = (threadIdx.x < SCAN_NB) ? g_bsum[threadIdx.x] : 0;
    s[threadIdx.x] = v;
    __syncthreads();
#pragma unroll
    for (int off = 1; off < 256; off <<= 1) {
        int a = (threadIdx.x >= off) ? s[threadIdx.x - off] : 0;
        __syncthreads();
        s[threadIdx.x] += a;
        __syncthreads();
    }
    if (threadIdx.x < SCAN_NB) g_bsum[threadIdx.x] = s[threadIdx.x] - v;  // exclusive
}

__global__ void scan3_k() {
    int i = blockIdx.x * 256 + threadIdx.x;
    if (i < NSEG) {
        int p = g_rowptr[i] + g_bsum[blockIdx.x];
        g_rowptr[i] = p;
        g_cursor[i] = p;
    }
    if (i == 0) g_rowptr[NSEG] = NNZ;
}

__global__ void scatter_k(const int* __restrict__ rows,
                          const int* __restrict__ cols,
                          const float* __restrict__ vals) {
    int e = blockIdx.x * 256 + threadIdx.x;
    if (e < NNZ) {
        int r = e / E_PER_R;
        int seg = r * N_NODES + rows[e];
        int pos = atomicAdd(&g_cursor[seg], 1);
        g_ccol[pos] = cols[e];
        g_cval[pos] = vals[e];
    }
}

// ---------------- SpMM: y[row, r*512+d] = sum_e val * x[col][d] (tf32-rounded out) --
__global__ void __launch_bounds__(128) spmm_k(int insel) {
    const float4* __restrict__ x4 = (const float4*)(insel ? g_h : g_x);
    int seg = blockIdx.x;
    int r = seg / N_NODES;
    int row = seg - r * N_NODES;
    int s = g_rowptr[seg];
    int e = g_rowptr[seg + 1];
    int t = threadIdx.x;

    float4 acc0 = make_float4(0.f, 0.f, 0.f, 0.f);
    float4 acc1 = make_float4(0.f, 0.f, 0.f, 0.f);

    int i = s;
    for (; i + 1 < e; i += 2) {
        int c0 = __ldg(&g_ccol[i]);
        int c1 = __ldg(&g_ccol[i + 1]);
        float v0 = __ldg(&g_cval[i]);
        float v1 = __ldg(&g_cval[i + 1]);
        float4 t0 = x4[(size_t)c0 * 128 + t];
        float4 t1 = x4[(size_t)c1 * 128 + t];
        acc0.x += v0 * t0.x; acc0.y += v0 * t0.y; acc0.z += v0 * t0.z; acc0.w += v0 * t0.w;
        acc1.x += v1 * t1.x; acc1.y += v1 * t1.y; acc1.z += v1 * t1.z; acc1.w += v1 * t1.w;
    }
    if (i < e) {
        int c0 = __ldg(&g_ccol[i]);
        float v0 = __ldg(&g_cval[i]);
        float4 t0 = x4[(size_t)c0 * 128 + t];
        acc0.x += v0 * t0.x; acc0.y += v0 * t0.y; acc0.z += v0 * t0.z; acc0.w += v0 * t0.w;
    }
    float4 o;
    o.x = tf32r(acc0.x + acc1.x);
    o.y = tf32r(acc0.y + acc1.y);
    o.z = tf32r(acc0.z + acc1.z);
    o.w = tf32r(acc0.w + acc1.w);
    ((float4*)g_y)[(size_t)row * (KBIG / 4) + r * (D / 4) + t] = o;
}

// ---------------- mma.sync tf32 GEMM: C = tanh(g_y[M,2560] @ WT^T) -----------------
// Block tile 128x128, BK=32, double-buffered cp.async. 8 warps, warp tile 32x64.
#define LDAS 36                       // floats per smem row (32 + 4 pad)
#define TBUF (128 * LDAS)             // 4608 floats per tile
#define GEMM_SMEM_BYTES (4 * TBUF * 4)  // A0 B0 A1 B1 = 73728 B

__device__ __forceinline__ void cp16(uint32_t dst, const float* src, uint32_t sz) {
    asm volatile("cp.async.cg.shared.global [%0], [%1], 16, %2;"
                 :: "r"(dst), "l"(src), "r"(sz));
}

__device__ __forceinline__ void gemm_prefetch(const float* __restrict__ A,
                                              const float* __restrict__ BT,
                                              float* as, float* bs,
                                              int kc, int m0, int n0, int tid) {
    int k0 = kc * 32;
#pragma unroll
    for (int i = 0; i < 4; ++i) {
        int idx = tid + i * 256;      // 0..1023
        int row = idx >> 3, c4 = idx & 7;
        int m = m0 + row;
        const float* src = A + (size_t)(m < N_NODES ? m : 0) * KBIG + k0 + c4 * 4;
        cp16(smem_u32(as + row * LDAS + c4 * 4), src, (m < N_NODES) ? 16u : 0u);
    }
#pragma unroll
    for (int i = 0; i < 4; ++i) {
        int idx = tid + i * 256;
        int row = idx >> 3, c4 = idx & 7;
        const float* src = BT + (size_t)(n0 + row) * KBIG + k0 + c4 * 4;
        cp16(smem_u32(bs + row * LDAS + c4 * 4), src, 16u);
    }
    asm volatile("cp.async.commit_group;" ::: "memory");
}

__global__ void __launch_bounds__(256) gemm_mma(const float* __restrict__ BT, int outsel) {
    extern __shared__ float sm[];
    const float* __restrict__ A = g_y;
    float* __restrict__ C = outsel ? g_emb : g_h;

    int tid = threadIdx.x;
    int wid = tid >> 5, lane = tid & 31;
    int wm = wid & 3, wn = wid >> 2;      // warp tile: rows wm*32, cols wn*64
    int g = lane >> 2, t4 = lane & 3;
    int m0 = blockIdx.x * 128;
    int n0 = blockIdx.y * 128;

    float acc[2][8][4];
#pragma unroll
    for (int mi = 0; mi < 2; ++mi)
#pragma unroll
        for (int ni = 0; ni < 8; ++ni)
#pragma unroll
            for (int j = 0; j < 4; ++j) acc[mi][ni][j] = 0.f;

    gemm_prefetch(A, BT, sm, sm + TBUF, 0, m0, n0, tid);

    for (int kc = 0; kc < NCHUNK; ++kc) {
        int b = kc & 1;
        if (kc + 1 < NCHUNK) {
            gemm_prefetch(A, BT, sm + (b ^ 1) * 2 * TBUF, sm + (b ^ 1) * 2 * TBUF + TBUF,
                          kc + 1, m0, n0, tid);
            asm volatile("cp.async.wait_group 1;" ::: "memory");
        } else {
            asm volatile("cp.async.wait_group 0;" ::: "memory");
        }
        __syncthreads();

        const uint32_t* asu = (const uint32_t*)(sm + b * 2 * TBUF);
        const uint32_t* bsu = asu + TBUF;
#pragma unroll
        for (int ks = 0; ks < 4; ++ks) {
            int kk = ks * 8;
            uint32_t af[2][4], bf[8][2];
#pragma unroll
            for (int mi = 0; mi < 2; ++mi) {
                int r0 = wm * 32 + mi * 16 + g;
                af[mi][0] = asu[r0 * LDAS + kk + t4];
                af[mi][1] = asu[(r0 + 8) * LDAS + kk + t4];
                af[mi][2] = asu[r0 * LDAS + kk + t4 + 4];
                af[mi][3] = asu[(r0 + 8) * LDAS + kk + t4 + 4];
            }
#pragma unroll
            for (int ni = 0; ni < 8; ++ni) {
                int c0 = wn * 64 + ni * 8 + g;
                bf[ni][0] = bsu[c0 * LDAS + kk + t4];
                bf[ni][1] = bsu[c0 * LDAS + kk + t4 + 4];
            }
#pragma unroll
            for (int mi = 0; mi < 2; ++mi)
#pragma unroll
                for (int ni = 0; ni < 8; ++ni) {
                    asm volatile(
                        "mma.sync.aligned.m16n8k8.row.col.f32.tf32.tf32.f32 "
                        "{%0,%1,%2,%3}, {%4,%5,%6,%7}, {%8,%9}, {%0,%1,%2,%3};"
                        : "+f"(acc[mi][ni][0]), "+f"(acc[mi][ni][1]),
                          "+f"(acc[mi][ni][2]), "+f"(acc[mi][ni][3])
                        : "r"(af[mi][0]), "r"(af[mi][1]), "r"(af[mi][2]), "r"(af[mi][3]),
                          "r"(bf[ni][0]), "r"(bf[ni][1]));
                }
        }
        __syncthreads();
    }

    // epilogue: c0/c1 -> (row, 2*t4 .. +1), c2/c3 -> (row+8, ...)
#pragma unroll
    for (int mi = 0; mi < 2; ++mi) {
        int row = m0 + wm * 32 + mi * 16 + g;
#pragma unroll
        for (int ni = 0; ni < 8; ++ni) {
            int col = n0 + wn * 64 + ni * 8 + 2 * t4;
            if (row < N_NODES) {
                float2 o0 = make_float2(tanhf(acc[mi][ni][0]), tanhf(acc[mi][ni][1]));
                *(float2*)(C + (size_t)row * D + col) = o0;
            }
            if (row + 8 < N_NODES) {
                float2 o1 = make_float2(tanhf(acc[mi][ni][2]), tanhf(acc[mi][ni][3]));
                *(float2*)(C + (size_t)(row + 8) * D + col) = o1;
            }
        }
    }
}

// ---------------- small GEMM (M=32), split-K with atomic accumulate ----------------
template <bool BT>
__global__ void __launch_bounds__(256) sgemm_k(int asel, const float* Ain,
                                               int wsel, const float* Win,
                                               int csel, float* Cin,
                                               int K, int N, int ldc) {
    __shared__ float sA[32 * 33];
    __shared__ float sW[64 * 33];

    const float* __restrict__ A = (asel < 0) ? Ain : bufptr(asel);
    const float* __restrict__ W = (wsel < 0) ? Win : bufptr(wsel);
    float* __restrict__ C = (csel < 0) ? Cin : bufptr(csel);

    int tid = threadIdx.x;
    int tx = tid & 31;
    int ty = tid >> 5;
    int j0 = blockIdx.x * 64;
    int k0 = blockIdx.y * 256;

    float acc[4][2];
#pragma unroll
    for (int i = 0; i < 4; ++i) { acc[i][0] = 0.f; acc[i][1] = 0.f; }

    for (int kc = 0; kc < 256; kc += 32) {
        int kb = k0 + kc;
        for (int i = tid; i < 32 * 32; i += 256) {
            int kk = i & 31, bb = i >> 5;
            sA[kk * 33 + bb] = A[(size_t)bb * K + kb + kk];
        }
        if (!BT) {
            for (int i = tid; i < 64 * 32; i += 256) {
                int jl = i & 63, kk = i >> 6;
                int j = j0 + jl;
                sW[kk * 65 + jl] = (j < N) ? W[(size_t)(kb + kk) * N + j] : 0.f;
            }
        } else {
            for (int i = tid; i < 64 * 32; i += 256) {
                int kk = i & 31, jl = i >> 5;
                int j = j0 + jl;
                sW[jl * 33 + kk] = (j < N) ? W[(size_t)j * K + kb + kk] : 0.f;
            }
        }
        __syncthreads();
#pragma unroll 8
        for (int kk = 0; kk < 32; ++kk) {
            float w0 = BT ? sW[tx * 33 + kk] : sW[kk * 65 + tx];
            float w1 = BT ? sW[(tx + 32) * 33 + kk] : sW[kk * 65 + tx + 32];
#pragma unroll
            for (int i = 0; i < 4; ++i) {
                float a = sA[kk * 33 + ty + 8 * i];
                acc[i][0] += a * w0;
                acc[i][1] += a * w1;
            }
        }
        __syncthreads();
    }
#pragma unroll
    for (int i = 0; i < 4; ++i) {
        int b = ty + 8 * i;
        int j = j0 + tx;
        if (j < N) atomicAdd(&C[(size_t)b * ldc + j], acc[i][0]);
        j = j0 + tx + 32;
        if (j < N) atomicAdd(&C[(size_t)b * ldc + j], acc[i][1]);
    }
}

__global__ void bias_act_k(int csel, const float* __restrict__ bias, int N, int act) {
    int idx = blockIdx.x * 256 + threadIdx.x;
    if (idx >= BATCH * N) return;
    float* C = bufptr(csel);
    int j = idx % N;
    float v = C[idx] + bias[j];
    if (act == 1) v = fmaxf(v, 0.f);
    else if (act == 2) v = tanhf(v);
    C[idx] = v;
}

__global__ void fgather_k(const int* __restrict__ gold, const int* __restrict__ flist,
                          float* __restrict__ out) {
    int b = blockIdx.x;
    int t = threadIdx.x; // 128
    int label = flist[b * 16 + gold[b]];
    ((float4*)(out + (size_t)b * OUTW + FRAME))[t] =
        ((const float4*)(g_emb + (size_t)label * D))[t];
}

// ---------------- launcher ----------------
extern "C" void kernel_launch(void* const* d_in, const int* in_sizes, int n_in,
                              void* d_out, int out_size) {
    const float* target_span = (const float*)d_in[0];
    const float* frame_emb   = (const float*)d_in[1];
    const float* role_emb    = (const float*)d_in[2];
    const float* rel_W0      = (const float*)d_in[3];
    const float* rel_W1      = (const float*)d_in[4];
    const float* span_W1     = (const float*)d_in[5];
    const float* span_b1     = (const float*)d_in[6];
    const float* span_W2     = (const float*)d_in[7];
    const float* span_b2     = (const float*)d_in[8];
    const float* fp_W1       = (const float*)d_in[9];
    const float* fp_b1       = (const float*)d_in[10];
    const float* fp_W2       = (const float*)d_in[11];
    const float* fp_b2       = (const float*)d_in[12];
    const float* adj_vals    = (const float*)d_in[13];
    const int*   fe_ids      = (const int*)d_in[14];
    const int*   adj_rows    = (const int*)d_in[15];
    const int*   adj_cols    = (const int*)d_in[16];
    const int*   gold        = (const int*)d_in[17];
    const int*   flist       = (const int*)d_in[18];
    float* out = (float*)d_out;

    static float* wt0_ptr = nullptr;
    static float* wt1_ptr = nullptr;
    if (!wt0_ptr) {
        cudaGetSymbolAddress((void**)&wt0_ptr, g_wt0);
        cudaGetSymbolAddress((void**)&wt1_ptr, g_wt1);
        cudaFuncSetAttribute(gemm_mma, cudaFuncAttributeMaxDynamicSharedMemorySize,
                             GEMM_SMEM_BYTES);
    }

    zero_k<<<256, 256>>>(out);
    build_x_k<<<N_NODES, 128>>>(frame_emb, role_emb, fe_ids);
    wtrans_k<<<dim3(KBIG / 32, D / 32), dim3(32, 8)>>>(rel_W0, wt0_ptr);
    wtrans_k<<<dim3(KBIG / 32, D / 32), dim3(32, 8)>>>(rel_W1, wt1_ptr);

    // CSR (shared by both layers)
    count_k<<<(NNZ + 255) / 256, 256>>>(adj_rows);
    scan1_k<<<SCAN_NB, 256>>>();
    scan2_k<<<1, 256>>>();
    scan3_k<<<SCAN_NB, 256>>>();
    scatter_k<<<(NNZ + 255) / 256, 256>>>(adj_rows, adj_cols, adj_vals);

    dim3 ggrid((N_NODES + 127) / 128, D / 128);
    // Layer 1: y = A x ; h = tanh(y @ W0_flat)
    spmm_k<<<NSEG, 128>>>(0);
    gemm_mma<<<ggrid, 256, GEMM_SMEM_BYTES>>>(wt0_ptr, 0);
    // Layer 2
    spmm_k<<<NSEG, 128>>>(1);
    gemm_mma<<<ggrid, 256, GEMM_SMEM_BYTES>>>(wt1_ptr, 1);

    // target_node = relu(ts @ W1 + b1) @ W2 + b2
    sgemm_k<false><<<dim3(2048 / 64, 2048 / 256), 256>>>(-1, target_span, -1, span_W1, 1, nullptr, 2048, 2048, 2048);
    bias_act_k<<<(BATCH * 2048 + 255) / 256, 256>>>(1, span_b1, 2048, 1);
    sgemm_k<false><<<dim3(D / 64, 2048 / 256), 256>>>(1, nullptr, -1, span_W2, 2, nullptr, 2048, D, D);
    bias_act_k<<<(BATCH * D + 255) / 256, 256>>>(2, span_b2, D, 0);
    // Q = tanh(relu(tn @ fpW1 + b) @ fpW2 + b)
    sgemm_k<false><<<dim3(D / 64, D / 256), 256>>>(2, nullptr, -1, fp_W1, 3, nullptr, D, D, D);
    bias_act_k<<<(BATCH * D + 255) / 256, 256>>>(3, fp_b1, D, 1);
    sgemm_k<false><<<dim3(D / 64, D / 256), 256>>>(3, nullptr, -1, fp_W2, 4, nullptr, D, D, D);
    bias_act_k<<<(BATCH * D + 255) / 256, 256>>>(4, fp_b2, D, 2);

    // pred[b, n<1200] = Q[b,:] . emb[n,:]
    sgemm_k<true><<<dim3((FRAME + 63) / 64, D / 256), 256>>>(4, nullptr, 5, nullptr, -1, out, D, FRAME, OUTW);
    // frame_node gather into out[:, 1200:1712]
    fgather_k<<<BATCH, 128>>>(gold, flist, out);
}